// round 1
// baseline (speedup 1.0000x reference)
#include <cuda_runtime.h>
#include <math.h>
#include <float.h>

#define NB_ 4
#define S_ 2048
#define D_ 2048
#define H_ 16
#define DH_ 128
#define T_ (NB_*S_)

// Scratch (allocation-free rule: device globals)
__device__ float g_Q[(size_t)NB_*H_*S_*DH_];
__device__ float g_K[(size_t)NB_*H_*S_*DH_];
__device__ float g_V[(size_t)NB_*H_*S_*DH_];
__device__ float g_attn[(size_t)T_*D_];

// ---------------------------------------------------------------------------
// SGEMM: C[m][n] = sum_k A[m][k] * W[n][k]   (A: [8192,2048], W: [2048,2048])
// MODE 0: plain write, C row-major [M,N]
// MODE 1: RoPE + scatter to [B,H,S,DH]
// MODE 2: scatter to [B,H,S,DH]
// 128x128 tile, BK=16, 256 threads, 8x8 per thread, double buffered smem.
// ---------------------------------------------------------------------------
template<int MODE>
__global__ __launch_bounds__(256, 2)
void sgemm_bt(const float* __restrict__ A, const float* __restrict__ W,
              float* __restrict__ C, const int* __restrict__ pos) {
    __shared__ float As[2][16][132];
    __shared__ float Bs[2][16][132];

    const int tid = threadIdx.x;
    const int tx = tid & 15;
    const int ty = tid >> 4;
    const int m0 = blockIdx.y * 128;
    const int n0 = blockIdx.x * 128;

    const int lr = tid >> 2;          // 0..63
    const int lc = (tid & 3) << 2;    // 0,4,8,12

    const float* Ab = A + (size_t)(m0 + lr) * D_ + lc;
    const float* Wb = W + (size_t)(n0 + lr) * D_ + lc;

    float acc[8][8];
#pragma unroll
    for (int i = 0; i < 8; ++i)
#pragma unroll
        for (int j = 0; j < 8; ++j) acc[i][j] = 0.f;

    // preload tile 0
    {
#pragma unroll
        for (int p = 0; p < 2; ++p) {
            float4 av = *(const float4*)(Ab + (size_t)p * 64 * D_);
            As[0][lc + 0][lr + p * 64] = av.x;
            As[0][lc + 1][lr + p * 64] = av.y;
            As[0][lc + 2][lr + p * 64] = av.z;
            As[0][lc + 3][lr + p * 64] = av.w;
            float4 bv = *(const float4*)(Wb + (size_t)p * 64 * D_);
            Bs[0][lc + 0][lr + p * 64] = bv.x;
            Bs[0][lc + 1][lr + p * 64] = bv.y;
            Bs[0][lc + 2][lr + p * 64] = bv.z;
            Bs[0][lc + 3][lr + p * 64] = bv.w;
        }
    }
    __syncthreads();

    const int NKT = D_ / 16;
    for (int kt = 0; kt < NKT; ++kt) {
        const int cur = kt & 1;
        float4 pa0, pa1, pb0, pb1;
        if (kt < NKT - 1) {
            const int k0 = (kt + 1) * 16;
            pa0 = *(const float4*)(Ab + k0);
            pa1 = *(const float4*)(Ab + (size_t)64 * D_ + k0);
            pb0 = *(const float4*)(Wb + k0);
            pb1 = *(const float4*)(Wb + (size_t)64 * D_ + k0);
        }
#pragma unroll
        for (int k = 0; k < 16; ++k) {
            float4 a0 = *(const float4*)&As[cur][k][ty * 4];
            float4 a1 = *(const float4*)&As[cur][k][64 + ty * 4];
            float4 b0 = *(const float4*)&Bs[cur][k][tx * 4];
            float4 b1 = *(const float4*)&Bs[cur][k][64 + tx * 4];
            float af[8] = {a0.x, a0.y, a0.z, a0.w, a1.x, a1.y, a1.z, a1.w};
            float bf[8] = {b0.x, b0.y, b0.z, b0.w, b1.x, b1.y, b1.z, b1.w};
#pragma unroll
            for (int rr = 0; rr < 8; ++rr)
#pragma unroll
                for (int cc = 0; cc < 8; ++cc)
                    acc[rr][cc] += af[rr] * bf[cc];
        }
        if (kt < NKT - 1) {
            const int nb = cur ^ 1;
            As[nb][lc + 0][lr] = pa0.x;  As[nb][lc + 1][lr] = pa0.y;
            As[nb][lc + 2][lr] = pa0.z;  As[nb][lc + 3][lr] = pa0.w;
            As[nb][lc + 0][lr + 64] = pa1.x;  As[nb][lc + 1][lr + 64] = pa1.y;
            As[nb][lc + 2][lr + 64] = pa1.z;  As[nb][lc + 3][lr + 64] = pa1.w;
            Bs[nb][lc + 0][lr] = pb0.x;  Bs[nb][lc + 1][lr] = pb0.y;
            Bs[nb][lc + 2][lr] = pb0.z;  Bs[nb][lc + 3][lr] = pb0.w;
            Bs[nb][lc + 0][lr + 64] = pb1.x;  Bs[nb][lc + 1][lr + 64] = pb1.y;
            Bs[nb][lc + 2][lr + 64] = pb1.z;  Bs[nb][lc + 3][lr + 64] = pb1.w;
        }
        __syncthreads();
    }

    // epilogue
    int rows[8], cols[8];
#pragma unroll
    for (int rr = 0; rr < 8; ++rr)
        rows[rr] = m0 + ((rr < 4) ? (ty * 4 + rr) : (64 + ty * 4 + rr - 4));
#pragma unroll
    for (int cc = 0; cc < 8; ++cc)
        cols[cc] = n0 + ((cc < 4) ? (tx * 4 + cc) : (64 + tx * 4 + cc - 4));

    if (MODE == 0) {
#pragma unroll
        for (int rr = 0; rr < 8; ++rr) {
            float4 v0 = make_float4(acc[rr][0], acc[rr][1], acc[rr][2], acc[rr][3]);
            float4 v1 = make_float4(acc[rr][4], acc[rr][5], acc[rr][6], acc[rr][7]);
            *(float4*)(C + (size_t)rows[rr] * D_ + cols[0]) = v0;
            *(float4*)(C + (size_t)rows[rr] * D_ + cols[4]) = v1;
        }
    } else {
#pragma unroll
        for (int rr = 0; rr < 8; ++rr) {
            const int t = rows[rr];
            const int b = t >> 11;
            const int s = t & (S_ - 1);
            const float p = (float)pos[s];
#pragma unroll
            for (int cc = 0; cc < 8; cc += 2) {
                const int e = cols[cc];             // even global column
                const int h = e >> 7;
                const int j = e & 127;              // even
                const size_t dst = (((size_t)(b * H_ + h)) * S_ + s) * DH_ + j;
                const float x1 = acc[rr][cc];
                const float x2 = acc[rr][cc + 1];
                if (MODE == 1) {
                    // inv_freq = theta^(-j/128), theta = 10000
                    const float inv = expf(-(float)j * (9.210340371976184f / 128.0f));
                    const float ang = p * inv;
                    float sn, cs;
                    sincosf(ang, &sn, &cs);
                    *(float2*)(C + dst) = make_float2(x1 * cs - x2 * sn,
                                                      x1 * sn + x2 * cs);
                } else {
                    *(float2*)(C + dst) = make_float2(x1, x2);
                }
            }
        }
    }
}

// ---------------------------------------------------------------------------
// Flash attention, causal. One block per (b*h, q-tile of 128). 256 threads.
// Score tile 128x128, 8x8 per thread. P staged through the K smem buffer.
// smem: Qs[128][132] + Ks/P[128][129] + Vs[128][129]  = 199,680 bytes
// ---------------------------------------------------------------------------
__global__ __launch_bounds__(256, 1)
void flash_kernel() {
    extern __shared__ float sm[];
    float* Qs = sm;                      // 128*132
    float* Ks = sm + 128 * 132;          // 128*129 (reused as P)
    float* Vs = Ks + 128 * 129;          // 128*129

    const int tid = threadIdx.x;
    const int tx = tid & 15;
    const int ty = tid >> 4;
    const int bh = blockIdx.x;           // 0..63
    const int qt = blockIdx.y;           // 0..15
    const int q0 = qt * 128;
    const size_t base = (size_t)bh * S_ * DH_;

    // load Q tile
#pragma unroll
    for (int i = 0; i < 16; ++i) {
        const int idx = tid + i * 256;       // 0..4095 float4s
        const int r = idx >> 5;
        const int d4 = (idx & 31) << 2;
        float4 v = *(const float4*)(g_Q + base + (size_t)(q0 + r) * DH_ + d4);
        *(float4*)&Qs[r * 132 + d4] = v;
    }

    float o_acc[8][8];
    float m_i[8], l_i[8];
#pragma unroll
    for (int rr = 0; rr < 8; ++rr) {
        m_i[rr] = -1e30f;
        l_i[rr] = 0.f;
#pragma unroll
        for (int dd = 0; dd < 8; ++dd) o_acc[rr][dd] = 0.f;
    }

    for (int kt = 0; kt <= qt; ++kt) {
        __syncthreads();  // prev-iter P/V readers done; Q-load visible on iter 0
        const int j0 = kt * 128;
#pragma unroll
        for (int i = 0; i < 16; ++i) {
            const int idx = tid + i * 256;
            const int c = idx >> 5;
            const int d4 = (idx & 31) << 2;
            float4 kv = *(const float4*)(g_K + base + (size_t)(j0 + c) * DH_ + d4);
            float4 vv = *(const float4*)(g_V + base + (size_t)(j0 + c) * DH_ + d4);
            const int so = c * 129 + d4;
            Ks[so + 0] = kv.x; Ks[so + 1] = kv.y; Ks[so + 2] = kv.z; Ks[so + 3] = kv.w;
            Vs[so + 0] = vv.x; Vs[so + 1] = vv.y; Vs[so + 2] = vv.z; Vs[so + 3] = vv.w;
        }
        __syncthreads();

        // scores: acc[rr][cc] = sum_d Q[ty*8+rr][d] * K[tx+cc*16][d]
        float acc[8][8];
#pragma unroll
        for (int rr = 0; rr < 8; ++rr)
#pragma unroll
            for (int cc = 0; cc < 8; ++cc) acc[rr][cc] = 0.f;

#pragma unroll 4
        for (int d = 0; d < 128; ++d) {
            float qf[8], kf[8];
#pragma unroll
            for (int rr = 0; rr < 8; ++rr) qf[rr] = Qs[(ty * 8 + rr) * 132 + d];
#pragma unroll
            for (int cc = 0; cc < 8; ++cc) kf[cc] = Ks[(tx + cc * 16) * 129 + d];
#pragma unroll
            for (int rr = 0; rr < 8; ++rr)
#pragma unroll
                for (int cc = 0; cc < 8; ++cc)
                    acc[rr][cc] += qf[rr] * kf[cc];
        }

        const float sc = 0.08838834764831845f;  // 1/sqrt(128)
        if (kt == qt) {
#pragma unroll
            for (int rr = 0; rr < 8; ++rr)
#pragma unroll
                for (int cc = 0; cc < 8; ++cc) {
                    const int crel = tx + cc * 16;
                    const int rrel = ty * 8 + rr;
                    acc[rr][cc] = (crel > rrel) ? -1e30f : acc[rr][cc] * sc;
                }
        } else {
#pragma unroll
            for (int rr = 0; rr < 8; ++rr)
#pragma unroll
                for (int cc = 0; cc < 8; ++cc) acc[rr][cc] *= sc;
        }

        // online softmax (row reduce over 16 lanes sharing ty)
#pragma unroll
        for (int rr = 0; rr < 8; ++rr) {
            float rmax = acc[rr][0];
#pragma unroll
            for (int cc = 1; cc < 8; ++cc) rmax = fmaxf(rmax, acc[rr][cc]);
#pragma unroll
            for (int off = 8; off > 0; off >>= 1)
                rmax = fmaxf(rmax, __shfl_xor_sync(0xffffffffu, rmax, off, 16));
            const float mnew = fmaxf(m_i[rr], rmax);
            const float alpha = __expf(m_i[rr] - mnew);
            float rs = 0.f;
#pragma unroll
            for (int cc = 0; cc < 8; ++cc) {
                const float v = __expf(acc[rr][cc] - mnew);
                acc[rr][cc] = v;
                rs += v;
            }
#pragma unroll
            for (int off = 8; off > 0; off >>= 1)
                rs += __shfl_xor_sync(0xffffffffu, rs, off, 16);
            l_i[rr] = l_i[rr] * alpha + rs;
            m_i[rr] = mnew;
#pragma unroll
            for (int dd = 0; dd < 8; ++dd) o_acc[rr][dd] *= alpha;
        }

        __syncthreads();  // all lanes done reading Ks as K
#pragma unroll
        for (int rr = 0; rr < 8; ++rr)
#pragma unroll
            for (int cc = 0; cc < 8; ++cc)
                Ks[(ty * 8 + rr) * 129 + tx + cc * 16] = acc[rr][cc];
        __syncthreads();

        // O += P @ V
#pragma unroll 4
        for (int c = 0; c < 128; ++c) {
            float pf[8], vf[8];
#pragma unroll
            for (int rr = 0; rr < 8; ++rr) pf[rr] = Ks[(ty * 8 + rr) * 129 + c];
#pragma unroll
            for (int dd = 0; dd < 8; ++dd) vf[dd] = Vs[c * 129 + tx + dd * 16];
#pragma unroll
            for (int rr = 0; rr < 8; ++rr)
#pragma unroll
                for (int dd = 0; dd < 8; ++dd)
                    o_acc[rr][dd] += pf[rr] * vf[dd];
        }
    }

    // write normalized O to [B,S,H*DH] layout for the output projection
    const int b = bh >> 4;
    const int h = bh & 15;
#pragma unroll
    for (int rr = 0; rr < 8; ++rr) {
        const int s = q0 + ty * 8 + rr;
        const float inv = 1.0f / l_i[rr];
        float* dst = g_attn + (size_t)(b * S_ + s) * D_ + h * DH_;
#pragma unroll
        for (int dd = 0; dd < 8; ++dd)
            dst[tx + dd * 16] = o_acc[rr][dd] * inv;
    }
}

// ---------------------------------------------------------------------------
extern "C" void kernel_launch(void* const* d_in, const int* in_sizes, int n_in,
                              void* d_out, int out_size) {
    const float* x  = (const float*)d_in[0];
    const int*   tp = (const int*)d_in[1];
    const float* wq = (const float*)d_in[2];
    const float* wk = (const float*)d_in[3];
    const float* wv = (const float*)d_in[4];
    const float* wo = (const float*)d_in[5];
    float* out = (float*)d_out;

    float *Q, *K, *V, *AT;
    cudaGetSymbolAddress((void**)&Q,  g_Q);
    cudaGetSymbolAddress((void**)&K,  g_K);
    cudaGetSymbolAddress((void**)&V,  g_V);
    cudaGetSymbolAddress((void**)&AT, g_attn);

    const int smem_flash = (128 * 132 + 2 * 128 * 129) * 4;  // 199,680 B
    cudaFuncSetAttribute(flash_kernel,
                         cudaFuncAttributeMaxDynamicSharedMemorySize, smem_flash);

    dim3 gemm_grid(D_ / 128, T_ / 128);  // (16, 64)
    sgemm_bt<1><<<gemm_grid, 256>>>(x, wq, Q, tp);
    sgemm_bt<1><<<gemm_grid, 256>>>(x, wk, K, tp);
    sgemm_bt<2><<<gemm_grid, 256>>>(x, wv, V, tp);

    flash_kernel<<<dim3(NB_ * H_, S_ / 128), 256, smem_flash>>>();

    sgemm_bt<0><<<gemm_grid, 256>>>(AT, wo, out, tp);
}

// round 2
// speedup vs baseline: 1.1281x; 1.1281x over previous
#include <cuda_runtime.h>
#include <math.h>

#define NB_ 4
#define S_ 2048
#define D_ 2048
#define H_ 16
#define DH_ 128
#define T_ (NB_*S_)

typedef unsigned long long u64;

// ---- packed f32x2 helpers (sm_103a) ----
__device__ __forceinline__ void fma2(u64 &acc, u64 a, u64 b) {
    asm("fma.rn.f32x2 %0, %1, %2, %0;" : "+l"(acc) : "l"(a), "l"(b));
}
__device__ __forceinline__ u64 dup2(float a) {
    u64 r; asm("mov.b64 %0, {%1, %1};" : "=l"(r) : "f"(a)); return r;
}
__device__ __forceinline__ float2 upk(u64 v) {
    float2 f; asm("mov.b64 {%0, %1}, %2;" : "=f"(f.x), "=f"(f.y) : "l"(v)); return f;
}
__device__ __forceinline__ void mul2i(u64 &acc, u64 a) {
    asm("mul.rn.f32x2 %0, %0, %1;" : "+l"(acc) : "l"(a));
}

// Scratch (allocation-free rule: device globals)
__device__ float g_Q[(size_t)NB_*H_*S_*DH_];   // [bh][d][s]  (head-transposed)
__device__ float g_K[(size_t)NB_*H_*S_*DH_];   // [bh][d][s]  (head-transposed)
__device__ float g_V[(size_t)NB_*H_*S_*DH_];   // [bh][s][d]
__device__ float g_attn[(size_t)T_*D_];

// ---------------------------------------------------------------------------
// SGEMM: C[m][n] = sum_k A[m][k] * W[n][k]
// MODE 0: plain write, C row-major [M,N]
// MODE 1: RoPE + transposed scatter to [bh][d][s]   (Q, K)
// MODE 2: scatter to [bh][s][d]                     (V)
// 128x128 tile, BK=16, 256 threads, 8x8 per thread, FFMA2 inner loop.
// ---------------------------------------------------------------------------
template<int MODE>
__global__ __launch_bounds__(256, 2)
void sgemm_bt(const float* __restrict__ A, const float* __restrict__ W,
              float* __restrict__ C, const int* __restrict__ pos) {
    __shared__ __align__(16) float As[2][16][132];
    __shared__ __align__(16) float Bs[2][16][132];

    const int tid = threadIdx.x;
    const int tx = tid & 15;
    const int ty = tid >> 4;
    const int m0 = blockIdx.y * 128;
    const int n0 = blockIdx.x * 128;

    const int lr = tid >> 2;          // 0..63
    const int lc = (tid & 3) << 2;    // 0,4,8,12

    const float* Ab = A + (size_t)(m0 + lr) * D_ + lc;
    const float* Wb = W + (size_t)(n0 + lr) * D_ + lc;

    u64 acc2[8][4];
#pragma unroll
    for (int i = 0; i < 8; ++i)
#pragma unroll
        for (int j = 0; j < 4; ++j) acc2[i][j] = 0ULL;

    // preload tile 0
    {
#pragma unroll
        for (int p = 0; p < 2; ++p) {
            float4 av = *(const float4*)(Ab + (size_t)p * 64 * D_);
            As[0][lc + 0][lr + p * 64] = av.x;
            As[0][lc + 1][lr + p * 64] = av.y;
            As[0][lc + 2][lr + p * 64] = av.z;
            As[0][lc + 3][lr + p * 64] = av.w;
            float4 bv = *(const float4*)(Wb + (size_t)p * 64 * D_);
            Bs[0][lc + 0][lr + p * 64] = bv.x;
            Bs[0][lc + 1][lr + p * 64] = bv.y;
            Bs[0][lc + 2][lr + p * 64] = bv.z;
            Bs[0][lc + 3][lr + p * 64] = bv.w;
        }
    }
    __syncthreads();

    const int NKT = D_ / 16;
    for (int kt = 0; kt < NKT; ++kt) {
        const int cur = kt & 1;
        float4 pa0, pa1, pb0, pb1;
        if (kt < NKT - 1) {
            const int k0 = (kt + 1) * 16;
            pa0 = *(const float4*)(Ab + k0);
            pa1 = *(const float4*)(Ab + (size_t)64 * D_ + k0);
            pb0 = *(const float4*)(Wb + k0);
            pb1 = *(const float4*)(Wb + (size_t)64 * D_ + k0);
        }
#pragma unroll
        for (int k = 0; k < 16; ++k) {
            float4 a0 = *(const float4*)&As[cur][k][ty * 4];
            float4 a1 = *(const float4*)&As[cur][k][64 + ty * 4];
            ulonglong2 b0 = *(const ulonglong2*)&Bs[cur][k][tx * 4];
            ulonglong2 b1 = *(const ulonglong2*)&Bs[cur][k][64 + tx * 4];
            float af[8] = {a0.x, a0.y, a0.z, a0.w, a1.x, a1.y, a1.z, a1.w};
#pragma unroll
            for (int rr = 0; rr < 8; ++rr) {
                u64 ad = dup2(af[rr]);
                fma2(acc2[rr][0], ad, b0.x);
                fma2(acc2[rr][1], ad, b0.y);
                fma2(acc2[rr][2], ad, b1.x);
                fma2(acc2[rr][3], ad, b1.y);
            }
        }
        if (kt < NKT - 1) {
            const int nb = cur ^ 1;
            As[nb][lc + 0][lr] = pa0.x;  As[nb][lc + 1][lr] = pa0.y;
            As[nb][lc + 2][lr] = pa0.z;  As[nb][lc + 3][lr] = pa0.w;
            As[nb][lc + 0][lr + 64] = pa1.x;  As[nb][lc + 1][lr + 64] = pa1.y;
            As[nb][lc + 2][lr + 64] = pa1.z;  As[nb][lc + 3][lr + 64] = pa1.w;
            Bs[nb][lc + 0][lr] = pb0.x;  Bs[nb][lc + 1][lr] = pb0.y;
            Bs[nb][lc + 2][lr] = pb0.z;  Bs[nb][lc + 3][lr] = pb0.w;
            Bs[nb][lc + 0][lr + 64] = pb1.x;  Bs[nb][lc + 1][lr + 64] = pb1.y;
            Bs[nb][lc + 2][lr + 64] = pb1.z;  Bs[nb][lc + 3][lr + 64] = pb1.w;
        }
        __syncthreads();
    }

    // unpack accumulators
    float pr[8][8];
#pragma unroll
    for (int rr = 0; rr < 8; ++rr)
#pragma unroll
        for (int g = 0; g < 4; ++g) {
            float2 f = upk(acc2[rr][g]);
            pr[rr][2 * g] = f.x;
            pr[rr][2 * g + 1] = f.y;
        }

    if (MODE == 0) {
        int rows[8];
#pragma unroll
        for (int rr = 0; rr < 8; ++rr)
            rows[rr] = m0 + ((rr < 4) ? (ty * 4 + rr) : (64 + ty * 4 + rr - 4));
#pragma unroll
        for (int rr = 0; rr < 8; ++rr) {
            *(float4*)(C + (size_t)rows[rr] * D_ + n0 + tx * 4) =
                make_float4(pr[rr][0], pr[rr][1], pr[rr][2], pr[rr][3]);
            *(float4*)(C + (size_t)rows[rr] * D_ + n0 + 64 + tx * 4) =
                make_float4(pr[rr][4], pr[rr][5], pr[rr][6], pr[rr][7]);
        }
    } else if (MODE == 1) {
        // RoPE in registers, then transposed coalesced stores to [bh][d][s]
        const int b = m0 >> 11;
        const int sbase = m0 & (S_ - 1);
#pragma unroll
        for (int rr = 0; rr < 8; ++rr) {
            const int s = sbase + ty * 4 + ((rr < 4) ? rr : (60 + rr));
            const float fp = (float)pos[s];
#pragma unroll
            for (int g = 0; g < 4; ++g) {
                const int cc0 = 2 * g;
                const int col0 = n0 + ((cc0 < 4) ? (tx * 4 + cc0) : (64 + tx * 4 + cc0 - 4));
                const int j = col0 & 127;  // even
                const float inv = expf(-(float)j * (9.210340371976184f / 128.0f));
                float sn, cs;
                sincosf(fp * inv, &sn, &cs);
                const float x1 = pr[rr][cc0], x2 = pr[rr][cc0 + 1];
                pr[rr][cc0]     = x1 * cs - x2 * sn;
                pr[rr][cc0 + 1] = x1 * sn + x2 * cs;
            }
        }
#pragma unroll
        for (int cc = 0; cc < 8; ++cc) {
            const int col = n0 + ((cc < 4) ? (tx * 4 + cc) : (64 + tx * 4 + cc - 4));
            const int h = col >> 7;
            const int j = col & 127;
            float* bse = C + ((size_t)(b * H_ + h) * DH_ + j) * S_ + sbase + ty * 4;
            *(float4*)bse =
                make_float4(pr[0][cc], pr[1][cc], pr[2][cc], pr[3][cc]);
            *(float4*)(bse + 64) =
                make_float4(pr[4][cc], pr[5][cc], pr[6][cc], pr[7][cc]);
        }
    } else {  // MODE 2: V scatter to [bh][s][d]
        int rows[8];
#pragma unroll
        for (int rr = 0; rr < 8; ++rr)
            rows[rr] = m0 + ((rr < 4) ? (ty * 4 + rr) : (64 + ty * 4 + rr - 4));
#pragma unroll
        for (int rr = 0; rr < 8; ++rr) {
            const int t = rows[rr];
            const int b = t >> 11;
            const int s = t & (S_ - 1);
#pragma unroll
            for (int cc = 0; cc < 8; cc += 2) {
                const int col = n0 + ((cc < 4) ? (tx * 4 + cc) : (64 + tx * 4 + cc - 4));
                const int h = col >> 7;
                const int j = col & 127;
                const size_t dst = (((size_t)(b * H_ + h)) * S_ + s) * DH_ + j;
                *(float2*)(C + dst) = make_float2(pr[rr][cc], pr[rr][cc + 1]);
            }
        }
    }
}

// ---------------------------------------------------------------------------
// Flash attention, causal, FFMA2. One block per (b*h, q-tile of 128).
// Qt/Kt in smem are d-major [d][col]; Vs is [c][d]; P staged transposed [c][q].
// smem: 3 * 128*132 floats = 202,752 bytes.
// ---------------------------------------------------------------------------
__global__ __launch_bounds__(256, 1)
void flash_kernel() {
    extern __shared__ __align__(16) float sm[];
    float* Qt = sm;                   // [d][q]
    float* Kt = sm + 128 * 132;       // [d][c], reused as Pt [c][q]
    float* Vs = sm + 2 * 128 * 132;   // [c][d]

    const int tid = threadIdx.x;
    const int tx = tid & 15;
    const int ty = tid >> 4;
    const int bh = blockIdx.x;
    const int qt = blockIdx.y;
    const int q0 = qt * 128;
    const size_t base = (size_t)bh * S_ * DH_;

    // load Q tile (d-major global -> straight copy)
#pragma unroll
    for (int i = 0; i < 16; ++i) {
        const int idx = tid + i * 256;
        const int r = idx >> 5;
        const int c4 = (idx & 31) << 2;
        float4 v = *(const float4*)(g_Q + base + (size_t)r * S_ + q0 + c4);
        *(float4*)&Qt[r * 132 + c4] = v;
    }

    u64 o2[8][4];
    float m_i[8], l_i[8];
#pragma unroll
    for (int rr = 0; rr < 8; ++rr) {
        m_i[rr] = -1e30f;
        l_i[rr] = 0.f;
#pragma unroll
        for (int g = 0; g < 4; ++g) o2[rr][g] = 0ULL;
    }

    for (int kt = 0; kt <= qt; ++kt) {
        __syncthreads();
        const int j0 = kt * 128;
#pragma unroll
        for (int i = 0; i < 16; ++i) {
            const int idx = tid + i * 256;
            const int r = idx >> 5;
            const int c4 = (idx & 31) << 2;
            float4 kv = *(const float4*)(g_K + base + (size_t)r * S_ + j0 + c4);
            *(float4*)&Kt[r * 132 + c4] = kv;
            float4 vv = *(const float4*)(g_V + base + (size_t)(j0 + r) * DH_ + c4);
            *(float4*)&Vs[r * 132 + c4] = vv;
        }
        __syncthreads();

        // scores: acc2[rr/2][cc] packed over q-row pairs
        u64 acc2[4][8];
#pragma unroll
        for (int a = 0; a < 4; ++a)
#pragma unroll
            for (int cc = 0; cc < 8; ++cc) acc2[a][cc] = 0ULL;

#pragma unroll 4
        for (int d = 0; d < 128; ++d) {
            ulonglong2 qA = *(const ulonglong2*)&Qt[d * 132 + ty * 8];
            ulonglong2 qB = *(const ulonglong2*)&Qt[d * 132 + ty * 8 + 4];
            float4 ka = *(const float4*)&Kt[d * 132 + tx * 8];
            float4 kb = *(const float4*)&Kt[d * 132 + tx * 8 + 4];
            float kf[8] = {ka.x, ka.y, ka.z, ka.w, kb.x, kb.y, kb.z, kb.w};
#pragma unroll
            for (int cc = 0; cc < 8; ++cc) {
                u64 kd = dup2(kf[cc]);
                fma2(acc2[0][cc], qA.x, kd);
                fma2(acc2[1][cc], qA.y, kd);
                fma2(acc2[2][cc], qB.x, kd);
                fma2(acc2[3][cc], qB.y, kd);
            }
        }

        // unpack + scale + causal mask
        const float sc = 0.08838834764831845f;  // 1/sqrt(128)
        float p[8][8];
#pragma unroll
        for (int a = 0; a < 4; ++a)
#pragma unroll
            for (int cc = 0; cc < 8; ++cc) {
                float2 f = upk(acc2[a][cc]);
                p[2 * a][cc] = f.x * sc;
                p[2 * a + 1][cc] = f.y * sc;
            }
        if (kt == qt) {
#pragma unroll
            for (int rr = 0; rr < 8; ++rr)
#pragma unroll
                for (int cc = 0; cc < 8; ++cc)
                    if (tx * 8 + cc > ty * 8 + rr) p[rr][cc] = -1e30f;
        }

        // online softmax (rows owned by 16 lanes sharing ty)
#pragma unroll
        for (int rr = 0; rr < 8; ++rr) {
            float rmax = p[rr][0];
#pragma unroll
            for (int cc = 1; cc < 8; ++cc) rmax = fmaxf(rmax, p[rr][cc]);
#pragma unroll
            for (int off = 8; off > 0; off >>= 1)
                rmax = fmaxf(rmax, __shfl_xor_sync(0xffffffffu, rmax, off, 16));
            const float mnew = fmaxf(m_i[rr], rmax);
            const float alpha = __expf(m_i[rr] - mnew);
            float rs = 0.f;
#pragma unroll
            for (int cc = 0; cc < 8; ++cc) {
                const float v = __expf(p[rr][cc] - mnew);
                p[rr][cc] = v;
                rs += v;
            }
#pragma unroll
            for (int off = 8; off > 0; off >>= 1)
                rs += __shfl_xor_sync(0xffffffffu, rs, off, 16);
            l_i[rr] = l_i[rr] * alpha + rs;
            m_i[rr] = mnew;
            u64 ad = dup2(alpha);
#pragma unroll
            for (int g = 0; g < 4; ++g) mul2i(o2[rr][g], ad);
        }

        __syncthreads();  // done reading Kt as K
        // store P transposed: Pt[c][q]
#pragma unroll
        for (int cc = 0; cc < 8; ++cc) {
            const int col = tx * 8 + cc;
            *(float4*)&Kt[col * 132 + ty * 8] =
                make_float4(p[0][cc], p[1][cc], p[2][cc], p[3][cc]);
            *(float4*)&Kt[col * 132 + ty * 8 + 4] =
                make_float4(p[4][cc], p[5][cc], p[6][cc], p[7][cc]);
        }
        __syncthreads();

        // O += P @ V   (packed over output-d pairs; P duplicated)
#pragma unroll 4
        for (int c = 0; c < 128; ++c) {
            float4 pa = *(const float4*)&Kt[c * 132 + ty * 8];
            float4 pb = *(const float4*)&Kt[c * 132 + ty * 8 + 4];
            ulonglong2 va = *(const ulonglong2*)&Vs[c * 132 + tx * 8];
            ulonglong2 vb = *(const ulonglong2*)&Vs[c * 132 + tx * 8 + 4];
            float pf[8] = {pa.x, pa.y, pa.z, pa.w, pb.x, pb.y, pb.z, pb.w};
#pragma unroll
            for (int rr = 0; rr < 8; ++rr) {
                u64 pd = dup2(pf[rr]);
                fma2(o2[rr][0], pd, va.x);
                fma2(o2[rr][1], pd, va.y);
                fma2(o2[rr][2], pd, vb.x);
                fma2(o2[rr][3], pd, vb.y);
            }
        }
    }

    // normalized O -> g_attn [b][s][h*128 + d]
    const int b = bh >> 4;
    const int h = bh & 15;
#pragma unroll
    for (int rr = 0; rr < 8; ++rr) {
        const int s = q0 + ty * 8 + rr;
        const float inv = 1.0f / l_i[rr];
        float* dst = g_attn + (size_t)(b * S_ + s) * D_ + h * DH_ + tx * 8;
        float2 f0 = upk(o2[rr][0]), f1 = upk(o2[rr][1]);
        float2 f2 = upk(o2[rr][2]), f3 = upk(o2[rr][3]);
        *(float4*)dst = make_float4(f0.x * inv, f0.y * inv, f1.x * inv, f1.y * inv);
        *(float4*)(dst + 4) = make_float4(f2.x * inv, f2.y * inv, f3.x * inv, f3.y * inv);
    }
}

// ---------------------------------------------------------------------------
extern "C" void kernel_launch(void* const* d_in, const int* in_sizes, int n_in,
                              void* d_out, int out_size) {
    const float* x  = (const float*)d_in[0];
    const int*   tp = (const int*)d_in[1];
    const float* wq = (const float*)d_in[2];
    const float* wk = (const float*)d_in[3];
    const float* wv = (const float*)d_in[4];
    const float* wo = (const float*)d_in[5];
    float* out = (float*)d_out;

    float *Q, *K, *V, *AT;
    cudaGetSymbolAddress((void**)&Q,  g_Q);
    cudaGetSymbolAddress((void**)&K,  g_K);
    cudaGetSymbolAddress((void**)&V,  g_V);
    cudaGetSymbolAddress((void**)&AT, g_attn);

    const int smem_flash = 3 * 128 * 132 * 4;  // 202,752 B
    cudaFuncSetAttribute(flash_kernel,
                         cudaFuncAttributeMaxDynamicSharedMemorySize, smem_flash);

    dim3 gemm_grid(D_ / 128, T_ / 128);  // (16, 64)
    sgemm_bt<1><<<gemm_grid, 256>>>(x, wq, Q, tp);
    sgemm_bt<1><<<gemm_grid, 256>>>(x, wk, K, tp);
    sgemm_bt<2><<<gemm_grid, 256>>>(x, wv, V, tp);

    flash_kernel<<<dim3(NB_ * H_, S_ / 128), 256, smem_flash>>>();

    sgemm_bt<0><<<gemm_grid, 256>>>(AT, wo, out, tp);
}

// round 4
// speedup vs baseline: 2.4672x; 2.1870x over previous
#include <cuda_runtime.h>
#include <math.h>
#include <cstdint>

#define NB_ 4
#define S_ 2048
#define D_ 2048
#define H_ 16
#define DH_ 128
#define T_ (NB_*S_)

typedef unsigned long long u64;
typedef unsigned int u32;

// tcgen05 is arch-accelerated: only legal when compiling the sm_103a target.
// The harness also emits a family-portable compute_103 PTX pass which must
// not see tcgen05 asm. Gate on the feature macro; fallback is correct-only.
#if !defined(__CUDA_ARCH__) || defined(__CUDA_ARCH_FEAT_SM103_ALL)
#define TC_EN 1
#else
#define TC_EN 0
#endif

// ---------------- packed f32x2 helpers (base sm_103 family: OK everywhere) --
__device__ __forceinline__ void fma2(u64 &acc, u64 a, u64 b) {
    asm("fma.rn.f32x2 %0, %1, %2, %0;" : "+l"(acc) : "l"(a), "l"(b));
}
__device__ __forceinline__ u64 dup2(float a) {
    u64 r; asm("mov.b64 %0, {%1, %1};" : "=l"(r) : "f"(a)); return r;
}
__device__ __forceinline__ float2 upk(u64 v) {
    float2 f; asm("mov.b64 {%0, %1}, %2;" : "=f"(f.x), "=f"(f.y) : "l"(v)); return f;
}
__device__ __forceinline__ void mul2i(u64 &acc, u64 a) {
    asm("mul.rn.f32x2 %0, %0, %1;" : "+l"(acc) : "l"(a));
}

// ---------------- generic helpers ----------------
__device__ __forceinline__ u32 smem_u32(const void* p) {
    u32 a;
    asm("{ .reg .u64 t; cvta.to.shared.u64 t, %1; cvt.u32.u64 %0, t; }"
        : "=r"(a) : "l"(p));
    return a;
}
__device__ __forceinline__ u32 elect1() {
    u32 p;
    asm volatile("{ .reg .pred p; elect.sync _|p, 0xFFFFFFFF; selp.b32 %0,1,0,p; }"
                 : "=r"(p));
    return p;
}
__device__ __forceinline__ float tf32r(float x) {
    u32 u; asm("cvt.rna.tf32.f32 %0, %1;" : "=r"(u) : "f"(x));
    return __uint_as_float(u);
}

#define MBAR_INIT(a, c) \
    asm volatile("mbarrier.init.shared.b64 [%0], %1;" :: "r"(a), "r"(c) : "memory")

#define MBAR_WAIT(a, ph) do { \
    u32 _m = (a), _p = (ph), _d; \
    asm volatile("{\n .reg .pred p;\n" \
        " mbarrier.try_wait.parity.acquire.cta.shared::cta.b64 p, [%1], %2;\n" \
        " selp.b32 %0,1,0,p;\n}" : "=r"(_d) : "r"(_m), "r"(_p) : "memory"); \
    if (!_d) { \
        asm volatile("{\n .reg .pred P;\n" \
            "LW%=:\n mbarrier.try_wait.parity.acquire.cta.shared::cta.b64 P, [%0], %1, 0x989680;\n" \
            " @P bra.uni LD%=;\n bra.uni LW%=;\nLD%=:\n}" \
            :: "r"(_m), "r"(_p) : "memory"); \
    } \
} while (0)

#if TC_EN
// ---------------- tcgen05 helpers (sm_103a only) ----------------
#define TC_ALLOC(sa, n) \
    asm volatile("tcgen05.alloc.cta_group::1.sync.aligned.shared::cta.b32 [%0], %1;" \
                 :: "r"(sa), "r"(n) : "memory")
#define TC_RELQ() \
    asm volatile("tcgen05.relinquish_alloc_permit.cta_group::1.sync.aligned;")
#define TC_DEALLOC(t, n) \
    asm volatile("tcgen05.dealloc.cta_group::1.sync.aligned.b32 %0, %1;" :: "r"(t), "r"(n))
#define TC_COMMIT(mb) \
    asm volatile("tcgen05.commit.cta_group::1.mbarrier::arrive::one.shared::cluster.b64 [%0];" \
                 :: "r"(mb) : "memory")
#define TC_FENCE_AFTER()  asm volatile("tcgen05.fence::after_thread_sync;" ::: "memory")
#define TC_WAIT_LD()      asm volatile("tcgen05.wait::ld.sync.aligned;" ::: "memory")
#define FENCE_ASYNC()     asm volatile("fence.proxy.async.shared::cta;" ::: "memory")

#define TC_LD_32X32B_X32(r, ta) \
    asm volatile( \
        "tcgen05.ld.sync.aligned.32x32b.x32.b32 " \
        "{%0, %1, %2, %3, %4, %5, %6, %7, " \
        " %8, %9, %10, %11, %12, %13, %14, %15, " \
        " %16, %17, %18, %19, %20, %21, %22, %23, " \
        " %24, %25, %26, %27, %28, %29, %30, %31}, [%32];" \
        : "=r"((r)[0]),  "=r"((r)[1]),  "=r"((r)[2]),  "=r"((r)[3]), \
          "=r"((r)[4]),  "=r"((r)[5]),  "=r"((r)[6]),  "=r"((r)[7]), \
          "=r"((r)[8]),  "=r"((r)[9]),  "=r"((r)[10]), "=r"((r)[11]), \
          "=r"((r)[12]), "=r"((r)[13]), "=r"((r)[14]), "=r"((r)[15]), \
          "=r"((r)[16]), "=r"((r)[17]), "=r"((r)[18]), "=r"((r)[19]), \
          "=r"((r)[20]), "=r"((r)[21]), "=r"((r)[22]), "=r"((r)[23]), \
          "=r"((r)[24]), "=r"((r)[25]), "=r"((r)[26]), "=r"((r)[27]), \
          "=r"((r)[28]), "=r"((r)[29]), "=r"((r)[30]), "=r"((r)[31]) \
        : "r"(ta))

// SS-mode tf32 MMA, cta_group::1, M=128 N=128, fp32 accumulate in TMEM.
__device__ __forceinline__ void mma_tf32(u32 dt, u64 ad, u64 bd, u32 idesc, bool acc) {
    u32 en = acc ? 1u : 0u;
    asm volatile("{\n .reg .pred p;\n setp.ne.u32 p, %4, 0;\n"
        " tcgen05.mma.cta_group::1.kind::tf32 [%0], %1, %2, %3, {%5,%5,%5,%5}, p;\n}"
        :: "r"(dt), "l"(ad), "l"(bd), "r"(idesc), "r"(en), "r"(0u) : "memory");
}
#endif  // TC_EN

// idesc: dtype=F32(1<<4), atype=TF32(2<<7), btype=TF32(2<<10), N=128(16<<17), M=128(8<<24)
static constexpr u32 IDESC_TF32 =
    (1u << 4) | (2u << 7) | (2u << 10) | ((128u / 8u) << 17) | ((128u / 16u) << 24);
// SW128 K-major descriptor base: layout=SW128(2), version=1, SBO=64, LBO=1
static constexpr u64 DESC_BASE =
    (2ull << 61) | (1ull << 46) | (64ull << 32) | (1ull << 16);
__device__ __forceinline__ u64 mk_desc(u32 addr) {
    return DESC_BASE | ((u64)(addr >> 4) & 0x3FFF);
}

// Scratch (allocation-free rule: device globals)
__device__ float g_Q[(size_t)NB_*H_*S_*DH_];   // [bh][d][s]  (head-transposed)
__device__ float g_K[(size_t)NB_*H_*S_*DH_];   // [bh][d][s]  (head-transposed)
__device__ float g_V[(size_t)NB_*H_*S_*DH_];   // [bh][s][d]
__device__ float g_attn[(size_t)T_*D_];

// ---------------------------------------------------------------------------
// tcgen05 tf32 GEMM: C[m][n] = sum_k A[m][k] * W[n][k]
// Tile 128x128, BK=32 (128B rows -> SW128), double-buffered smem, 128 threads.
// MODE 0: plain write C[M][N]
// MODE 1: RoPE + transposed scatter to [bh][d][s]
// MODE 2: scatter to [bh][s][d]
// ---------------------------------------------------------------------------
template<int MODE>
__global__ __launch_bounds__(128, 1)
void tc_gemm(const float* __restrict__ A, const float* __restrict__ W,
             float* __restrict__ C, const int* __restrict__ pos) {
    const int tid = threadIdx.x;
    const int wid = tid >> 5;
    const int lid = tid & 31;
    const int n0 = blockIdx.x * 128;
    const int m0 = blockIdx.y * 128;
    const int m = m0 + wid * 32 + lid;

    u32 d[128];

#if TC_EN
    extern __shared__ __align__(1024) char smem[];
    const u32 sb = smem_u32(smem);
    const u32 mbar0 = sb + 65536;
    const u32 mbar1 = sb + 65544;
    const u32 tmemp = sb + 65552;

    if (wid == 0) {
        TC_ALLOC(tmemp, 128);
        TC_RELQ();
    }
    if (tid == 0) { MBAR_INIT(mbar0, 1); MBAR_INIT(mbar1, 1); }
    __syncthreads();
    u32 tmem;
    asm volatile("ld.shared.b32 %0, [%1];" : "=r"(tmem) : "r"(tmemp));

    // load mapping: thread handles float4 column c4 of rows r0+16*i
    const int c4 = tid & 7;
    const int r0 = tid >> 3;
    const float* Agp = A + ((size_t)(m0 + r0)) * D_ + c4 * 4;
    const float* Wgp = W + ((size_t)(n0 + r0)) * D_ + c4 * 4;
    u32 soff = (u32)(r0 * 128 + c4 * 16);
    soff ^= (soff >> 3) & 0x70;   // SW128 swizzle (row stride 128B)

    int ph0 = 0, ph1 = 0;
    for (int kt = 0; kt < 64; ++kt) {
        const int cur = kt & 1;
        if (kt >= 2) {
            if (cur == 0) { MBAR_WAIT(mbar0, ph0); ph0 ^= 1; }
            else          { MBAR_WAIT(mbar1, ph1); ph1 ^= 1; }
        }
        const int kk = kt * 32;
        char* Ad = smem + cur * 16384;
        char* Bd = smem + 32768 + cur * 16384;
#pragma unroll
        for (int i = 0; i < 8; ++i) {
            float4 va = *(const float4*)(Agp + (size_t)(16 * i) * D_ + kk);
            float4 vb = *(const float4*)(Wgp + (size_t)(16 * i) * D_ + kk);
            const u32 off = soff + (u32)(i * 16 * 128);
            *(float4*)(Ad + off) = make_float4(tf32r(va.x), tf32r(va.y),
                                               tf32r(va.z), tf32r(va.w));
            *(float4*)(Bd + off) = make_float4(tf32r(vb.x), tf32r(vb.y),
                                               tf32r(vb.z), tf32r(vb.w));
        }
        FENCE_ASYNC();
        __syncthreads();
        if (wid == 0 && elect1()) {
            u64 ad = mk_desc(sb + cur * 16384);
            u64 bd = mk_desc(sb + 32768 + cur * 16384);
#pragma unroll
            for (int k = 0; k < 4; ++k)
                mma_tf32(tmem, ad + k * 2, bd + k * 2, IDESC_TF32, (kt > 0) || (k > 0));
            TC_COMMIT(cur == 0 ? mbar0 : mbar1);
        }
    }
    MBAR_WAIT(mbar0, ph0);
    MBAR_WAIT(mbar1, ph1);
    TC_FENCE_AFTER();

    // read D: lane owns row m = m0 + wid*32 + lid, 128 columns
    TC_LD_32X32B_X32(d +  0, tmem +  0);
    TC_LD_32X32B_X32(d + 32, tmem + 32);
    TC_LD_32X32B_X32(d + 64, tmem + 64);
    TC_LD_32X32B_X32(d + 96, tmem + 96);
    TC_WAIT_LD();
    __syncthreads();
    if (wid == 0) TC_DEALLOC(tmem, 128);
#else
    // Correct-only fallback for the family-portable (compute_103) pass.
    // Never executed on the bench GPU (sm_103a SASS takes precedence).
    for (int c = 0; c < 128; ++c) {
        float s = 0.f;
        const float* Ar = A + (size_t)m * D_;
        const float* Wr = W + (size_t)(n0 + c) * D_;
        for (int k = 0; k < D_; k += 4) {
            float4 a = *(const float4*)(Ar + k);
            float4 w = *(const float4*)(Wr + k);
            s += a.x * w.x + a.y * w.y + a.z * w.z + a.w * w.w;
        }
        d[c] = __float_as_uint(s);
    }
#endif

    if (MODE == 0) {
        float* dst = C + (size_t)m * D_ + n0;
#pragma unroll
        for (int c = 0; c < 128; c += 4)
            *(float4*)(dst + c) = make_float4(
                __uint_as_float(d[c]), __uint_as_float(d[c + 1]),
                __uint_as_float(d[c + 2]), __uint_as_float(d[c + 3]));
    } else if (MODE == 1) {
        const int b = m >> 11;
        const int s = m & (S_ - 1);
        const int bh = b * H_ + (n0 >> 7);
        const float fp = (float)pos[s];
#pragma unroll 8
        for (int g = 0; g < 64; ++g) {
            const int j = 2 * g;
            const float inv = expf(-(float)j * (9.210340371976184f / 128.0f));
            float sn, cs;
            sincosf(fp * inv, &sn, &cs);
            const float x1 = __uint_as_float(d[j]);
            const float x2 = __uint_as_float(d[j + 1]);
            d[j]     = __float_as_uint(x1 * cs - x2 * sn);
            d[j + 1] = __float_as_uint(x1 * sn + x2 * cs);
        }
        float* base = C + ((size_t)bh * DH_) * S_ + s;
#pragma unroll
        for (int j = 0; j < 128; ++j)
            base[(size_t)j * S_] = __uint_as_float(d[j]);   // lanes: consecutive s
    } else {  // MODE 2: V -> [bh][s][d]
        const int b = m >> 11;
        const int s = m & (S_ - 1);
        const int bh = b * H_ + (n0 >> 7);
        float* dst = C + ((size_t)bh * S_ + s) * DH_;
#pragma unroll
        for (int c = 0; c < 128; c += 4)
            *(float4*)(dst + c) = make_float4(
                __uint_as_float(d[c]), __uint_as_float(d[c + 1]),
                __uint_as_float(d[c + 2]), __uint_as_float(d[c + 3]));
    }
}

// ---------------------------------------------------------------------------
// Flash attention, causal, FFMA2 (unchanged; base-family instructions only).
// ---------------------------------------------------------------------------
__global__ __launch_bounds__(256, 1)
void flash_kernel() {
    extern __shared__ __align__(16) float sm[];
    float* Qt = sm;                   // [d][q]
    float* Kt = sm + 128 * 132;       // [d][c], reused as Pt [c][q]
    float* Vs = sm + 2 * 128 * 132;   // [c][d]

    const int tid = threadIdx.x;
    const int tx = tid & 15;
    const int ty = tid >> 4;
    const int bh = blockIdx.x;
    const int qt = blockIdx.y;
    const int q0 = qt * 128;
    const size_t base = (size_t)bh * S_ * DH_;

#pragma unroll
    for (int i = 0; i < 16; ++i) {
        const int idx = tid + i * 256;
        const int r = idx >> 5;
        const int c4 = (idx & 31) << 2;
        float4 v = *(const float4*)(g_Q + base + (size_t)r * S_ + q0 + c4);
        *(float4*)&Qt[r * 132 + c4] = v;
    }

    u64 o2[8][4];
    float m_i[8], l_i[8];
#pragma unroll
    for (int rr = 0; rr < 8; ++rr) {
        m_i[rr] = -1e30f;
        l_i[rr] = 0.f;
#pragma unroll
        for (int g = 0; g < 4; ++g) o2[rr][g] = 0ULL;
    }

    for (int kt = 0; kt <= qt; ++kt) {
        __syncthreads();
        const int j0 = kt * 128;
#pragma unroll
        for (int i = 0; i < 16; ++i) {
            const int idx = tid + i * 256;
            const int r = idx >> 5;
            const int c4 = (idx & 31) << 2;
            float4 kv = *(const float4*)(g_K + base + (size_t)r * S_ + j0 + c4);
            *(float4*)&Kt[r * 132 + c4] = kv;
            float4 vv = *(const float4*)(g_V + base + (size_t)(j0 + r) * DH_ + c4);
            *(float4*)&Vs[r * 132 + c4] = vv;
        }
        __syncthreads();

        u64 acc2[4][8];
#pragma unroll
        for (int a = 0; a < 4; ++a)
#pragma unroll
            for (int cc = 0; cc < 8; ++cc) acc2[a][cc] = 0ULL;

#pragma unroll 4
        for (int d = 0; d < 128; ++d) {
            ulonglong2 qA = *(const ulonglong2*)&Qt[d * 132 + ty * 8];
            ulonglong2 qB = *(const ulonglong2*)&Qt[d * 132 + ty * 8 + 4];
            float4 ka = *(const float4*)&Kt[d * 132 + tx * 8];
            float4 kb = *(const float4*)&Kt[d * 132 + tx * 8 + 4];
            float kf[8] = {ka.x, ka.y, ka.z, ka.w, kb.x, kb.y, kb.z, kb.w};
#pragma unroll
            for (int cc = 0; cc < 8; ++cc) {
                u64 kd = dup2(kf[cc]);
                fma2(acc2[0][cc], qA.x, kd);
                fma2(acc2[1][cc], qA.y, kd);
                fma2(acc2[2][cc], qB.x, kd);
                fma2(acc2[3][cc], qB.y, kd);
            }
        }

        const float sc = 0.08838834764831845f;  // 1/sqrt(128)
        float p[8][8];
#pragma unroll
        for (int a = 0; a < 4; ++a)
#pragma unroll
            for (int cc = 0; cc < 8; ++cc) {
                float2 f = upk(acc2[a][cc]);
                p[2 * a][cc] = f.x * sc;
                p[2 * a + 1][cc] = f.y * sc;
            }
        if (kt == qt) {
#pragma unroll
            for (int rr = 0; rr < 8; ++rr)
#pragma unroll
                for (int cc = 0; cc < 8; ++cc)
                    if (tx * 8 + cc > ty * 8 + rr) p[rr][cc] = -1e30f;
        }

#pragma unroll
        for (int rr = 0; rr < 8; ++rr) {
            float rmax = p[rr][0];
#pragma unroll
            for (int cc = 1; cc < 8; ++cc) rmax = fmaxf(rmax, p[rr][cc]);
#pragma unroll
            for (int off = 8; off > 0; off >>= 1)
                rmax = fmaxf(rmax, __shfl_xor_sync(0xffffffffu, rmax, off, 16));
            const float mnew = fmaxf(m_i[rr], rmax);
            const float alpha = __expf(m_i[rr] - mnew);
            float rs = 0.f;
#pragma unroll
            for (int cc = 0; cc < 8; ++cc) {
                const float v = __expf(p[rr][cc] - mnew);
                p[rr][cc] = v;
                rs += v;
            }
#pragma unroll
            for (int off = 8; off > 0; off >>= 1)
                rs += __shfl_xor_sync(0xffffffffu, rs, off, 16);
            l_i[rr] = l_i[rr] * alpha + rs;
            m_i[rr] = mnew;
            u64 ad = dup2(alpha);
#pragma unroll
            for (int g = 0; g < 4; ++g) mul2i(o2[rr][g], ad);
        }

        __syncthreads();
#pragma unroll
        for (int cc = 0; cc < 8; ++cc) {
            const int col = tx * 8 + cc;
            *(float4*)&Kt[col * 132 + ty * 8] =
                make_float4(p[0][cc], p[1][cc], p[2][cc], p[3][cc]);
            *(float4*)&Kt[col * 132 + ty * 8 + 4] =
                make_float4(p[4][cc], p[5][cc], p[6][cc], p[7][cc]);
        }
        __syncthreads();

#pragma unroll 4
        for (int c = 0; c < 128; ++c) {
            float4 pa = *(const float4*)&Kt[c * 132 + ty * 8];
            float4 pb = *(const float4*)&Kt[c * 132 + ty * 8 + 4];
            ulonglong2 va = *(const ulonglong2*)&Vs[c * 132 + tx * 8];
            ulonglong2 vb = *(const ulonglong2*)&Vs[c * 132 + tx * 8 + 4];
            float pf[8] = {pa.x, pa.y, pa.z, pa.w, pb.x, pb.y, pb.z, pb.w};
#pragma unroll
            for (int rr = 0; rr < 8; ++rr) {
                u64 pd = dup2(pf[rr]);
                fma2(o2[rr][0], pd, va.x);
                fma2(o2[rr][1], pd, va.y);
                fma2(o2[rr][2], pd, vb.x);
                fma2(o2[rr][3], pd, vb.y);
            }
        }
    }

    const int b = bh >> 4;
    const int h = bh & 15;
#pragma unroll
    for (int rr = 0; rr < 8; ++rr) {
        const int s = q0 + ty * 8 + rr;
        const float inv = 1.0f / l_i[rr];
        float* dst = g_attn + (size_t)(b * S_ + s) * D_ + h * DH_ + tx * 8;
        float2 f0 = upk(o2[rr][0]), f1 = upk(o2[rr][1]);
        float2 f2 = upk(o2[rr][2]), f3 = upk(o2[rr][3]);
        *(float4*)dst = make_float4(f0.x * inv, f0.y * inv, f1.x * inv, f1.y * inv);
        *(float4*)(dst + 4) = make_float4(f2.x * inv, f2.y * inv, f3.x * inv, f3.y * inv);
    }
}

// ---------------------------------------------------------------------------
extern "C" void kernel_launch(void* const* d_in, const int* in_sizes, int n_in,
                              void* d_out, int out_size) {
    const float* x  = (const float*)d_in[0];
    const int*   tp = (const int*)d_in[1];
    const float* wq = (const float*)d_in[2];
    const float* wk = (const float*)d_in[3];
    const float* wv = (const float*)d_in[4];
    const float* wo = (const float*)d_in[5];
    float* out = (float*)d_out;

    float *Q, *K, *V, *AT;
    cudaGetSymbolAddress((void**)&Q,  g_Q);
    cudaGetSymbolAddress((void**)&K,  g_K);
    cudaGetSymbolAddress((void**)&V,  g_V);
    cudaGetSymbolAddress((void**)&AT, g_attn);

    const int smem_gemm = 65536 + 64;
    cudaFuncSetAttribute(tc_gemm<0>, cudaFuncAttributeMaxDynamicSharedMemorySize, smem_gemm);
    cudaFuncSetAttribute(tc_gemm<1>, cudaFuncAttributeMaxDynamicSharedMemorySize, smem_gemm);
    cudaFuncSetAttribute(tc_gemm<2>, cudaFuncAttributeMaxDynamicSharedMemorySize, smem_gemm);

    const int smem_flash = 3 * 128 * 132 * 4;  // 202,752 B
    cudaFuncSetAttribute(flash_kernel,
                         cudaFuncAttributeMaxDynamicSharedMemorySize, smem_flash);

    dim3 gg(D_ / 128, T_ / 128);  // (16, 64)
    tc_gemm<1><<<gg, 128, smem_gemm>>>(x, wq, Q, tp);
    tc_gemm<1><<<gg, 128, smem_gemm>>>(x, wk, K, tp);
    tc_gemm<2><<<gg, 128, smem_gemm>>>(x, wv, V, tp);

    flash_kernel<<<dim3(NB_ * H_, S_ / 128), 256, smem_flash>>>();

    tc_gemm<0><<<gg, 128, smem_gemm>>>(AT, wo, out, tp);
}